// round 9
// baseline (speedup 1.0000x reference)
#include <cuda_runtime.h>

// Problem constants
#define HW2        65536      // 256*256 pixels
#define N_PIX      65536
#define N_Q        16384      // pixel quads (float4 granularity)
#define BATCH      64
#define NBLK_COV   1024       // 512 quad-groups x 2 batch-halves

// Scratch (allocation-free rule: __device__ globals)
__device__ float g_G2[2 * 6 * N_PIX];  // half-covariances: [half][plane][pix]
__device__ float g_mats[18 * N_PIX];   // A(9), 8L(6), d(3) — plane-major
__device__ float g_partial[NBLK_COV];  // per-block trace partial sums

// ---- float4 helpers --------------------------------------------------------
__device__ __forceinline__ float4 f4mul(float4 a, float4 b) {
    return make_float4(a.x * b.x, a.y * b.y, a.z * b.z, a.w * b.w);
}
__device__ __forceinline__ float4 f4fma(float4 a, float4 b, float4 c) {
    return make_float4(fmaf(a.x, b.x, c.x), fmaf(a.y, b.y, c.y),
                       fmaf(a.z, b.z, c.z), fmaf(a.w, b.w, c.w));
}
__device__ __forceinline__ float4 f4neg(float4 a) {
    return make_float4(-a.x, -a.y, -a.z, -a.w);
}
__device__ __forceinline__ float4 f4add(float4 a, float4 b) {
    return make_float4(a.x + b.x, a.y + b.y, a.z + b.z, a.w + b.w);
}
__device__ __forceinline__ float4 f4scale(float4 a, float s) {
    return make_float4(a.x * s, a.y * s, a.z * s, a.w * s);
}

// ---------------------------------------------------------------------------
// Kernel 1: half-covariance per block. Grid 1024 = (512 quad-groups) x (2 halves).
// Block = 8 warps; warp w accumulates 4 batches [half*32 + 4w, +4) for the
// block's 32 pixel-quads; shared reduction collapses the 8 warp partials.
// ~55 warps/SM resident -> enough MLP to saturate DRAM reads.
// ---------------------------------------------------------------------------
__global__ __launch_bounds__(256) void k_covar(const float4* __restrict__ s4) {
    const int lane = threadIdx.x & 31;
    const int w    = threadIdx.x >> 5;            // warp id 0..7
    const int half = blockIdx.x & 1;              // batch half
    const int qg   = blockIdx.x >> 1;             // quad group 0..511
    const int q    = qg * 32 + lane;              // pixel quad

    float4 a0 = make_float4(0.f, 0.f, 0.f, 0.f);
    float4 a1 = a0, a2 = a0, a3 = a0, a4 = a0, a5 = a0;

#pragma unroll
    for (int i = 0; i < 4; ++i) {
        const int b = half * 32 + w * 4 + i;
        const float4* base = s4 + (size_t)b * (3 * N_Q) + q;
        const float4 s0 = __ldcs(base);
        const float4 s1 = __ldcs(base + N_Q);
        const float4 s2 = __ldcs(base + 2 * N_Q);
        a0 = f4fma(s0, s0, a0); a1 = f4fma(s0, s1, a1); a2 = f4fma(s0, s2, a2);
        a3 = f4fma(s1, s1, a3); a4 = f4fma(s1, s2, a4); a5 = f4fma(s2, s2, a5);
    }

    __shared__ float4 sh[6][8][32];               // 24 KB
    sh[0][w][lane] = a0; sh[1][w][lane] = a1; sh[2][w][lane] = a2;
    sh[3][w][lane] = a3; sh[4][w][lane] = a4; sh[5][w][lane] = a5;
    __syncthreads();

    // threads 0..191: (plane, quad_local) — sum the 8 warp partials
    float tr = 0.f;
    const int t = threadIdx.x;
    if (t < 192) {
        const int pl = t >> 5;
        const int ql = t & 31;
        float4 acc = sh[pl][0][ql];
#pragma unroll
        for (int ww = 1; ww < 8; ++ww) acc = f4add(acc, sh[pl][ww][ql]);
        acc = f4scale(acc, 1.0f / 64.0f);
        ((float4*)g_G2)[(size_t)(half * 6 + pl) * N_Q + qg * 32 + ql] = acc;
        if (pl == 0 || pl == 3 || pl == 5)
            tr = acc.x + acc.y + acc.z + acc.w;
    }

    // block reduce trace contributions -> one partial per block
#pragma unroll
    for (int o = 16; o > 0; o >>= 1)
        tr += __shfl_down_sync(0xffffffffu, tr, o);
    __shared__ float shr[8];
    if (lane == 0) shr[w] = tr;
    __syncthreads();
    if (t == 0) {
        float acc = 0.f;
#pragma unroll
        for (int i = 0; i < 8; ++i) acc += shr[i];
        g_partial[blockIdx.x] = acc;
    }
}

// ---------------------------------------------------------------------------
// Kernel 2: reduce covariance halves + per-pixel matrix prep (fp32).
//   G = alpha*G/norm + (1-alpha)*0.25*I
//   A = 8*L*Ginv ; 8L ; d = sqrt(1.28)*rowsum(L)
//   (C = 0.64*G*Ginv == 0.64*I at fp32 rounding — folded into k_apply.)
// ---------------------------------------------------------------------------
__global__ __launch_bounds__(256) void k_prep(const float* __restrict__ t) {
    // reduce 1024 trace partials redundantly per block
    __shared__ float sh_sum;
    {
        float v = g_partial[threadIdx.x]       + g_partial[threadIdx.x + 256]
                + g_partial[threadIdx.x + 512] + g_partial[threadIdx.x + 768];
#pragma unroll
        for (int o = 16; o > 0; o >>= 1)
            v += __shfl_down_sync(0xffffffffu, v, o);
        __shared__ float sh[8];
        const int lane = threadIdx.x & 31;
        const int w    = threadIdx.x >> 5;
        if (lane == 0) sh[w] = v;
        __syncthreads();
        if (threadIdx.x == 0) {
            float acc = 0.f;
#pragma unroll
            for (int i = 0; i < 8; ++i) acc += sh[i];
            sh_sum = acc;
        }
        __syncthreads();
    }

    const int p = blockIdx.x * blockDim.x + threadIdx.x;
    const float t0 = __ldg(t);
    const float diag_mean = sh_sum / (65536.0f * 3.0f);
    const float norm  = (t0 == 1.0f) ? diag_mean * 4.0f : 1.0f;
    const float alpha = 0.5f * __expf(-4.5f * (1.0f - t0));
    const float sa = alpha / norm;
    const float diag_add = (1.0f - alpha) * 0.25f;

    // combine halves
    const float g00 = g_G2[0 * N_PIX + p] + g_G2[ 6 * N_PIX + p];
    const float g01 = g_G2[1 * N_PIX + p] + g_G2[ 7 * N_PIX + p];
    const float g02 = g_G2[2 * N_PIX + p] + g_G2[ 8 * N_PIX + p];
    const float g11 = g_G2[3 * N_PIX + p] + g_G2[ 9 * N_PIX + p];
    const float g12 = g_G2[4 * N_PIX + p] + g_G2[10 * N_PIX + p];
    const float g22 = g_G2[5 * N_PIX + p] + g_G2[11 * N_PIX + p];

    const float a00 = g00 * sa + diag_add;
    const float a01 = g01 * sa;
    const float a02 = g02 * sa;
    const float a11 = g11 * sa + diag_add;
    const float a12 = g12 * sa;
    const float a22 = g22 * sa + diag_add;

    // adjugate inverse (fp32)
    const float c00 = a11 * a22 - a12 * a12;
    const float c01 = a02 * a12 - a01 * a22;
    const float c02 = a01 * a12 - a02 * a11;
    const float det = a00 * c00 + a01 * c01 + a02 * c02;
    const float id  = 1.0f / det;
    const float i00 = c00 * id;
    const float i01 = c01 * id;
    const float i02 = c02 * id;
    const float i11 = (a00 * a22 - a02 * a02) * id;
    const float i12 = (a01 * a02 - a00 * a12) * id;
    const float i22 = (a00 * a11 - a01 * a01) * id;

    // Cholesky (fp32)
    const float l00 = sqrtf(a00);
    const float il00 = 1.0f / l00;
    const float l10 = a01 * il00;
    const float l20 = a02 * il00;
    const float l11 = sqrtf(a11 - l10 * l10);
    const float l21 = (a12 - l20 * l10) / l11;
    const float l22 = sqrtf(a22 - l20 * l20 - l21 * l21);

    // A = 8 * L * Ginv
    const float A00 = 8.0f * (l00 * i00);
    const float A01 = 8.0f * (l00 * i01);
    const float A02 = 8.0f * (l00 * i02);
    const float A10 = 8.0f * (l10 * i00 + l11 * i01);
    const float A11 = 8.0f * (l10 * i01 + l11 * i11);
    const float A12 = 8.0f * (l10 * i02 + l11 * i12);
    const float A20 = 8.0f * (l20 * i00 + l21 * i01 + l22 * i02);
    const float A21 = 8.0f * (l20 * i01 + l21 * i11 + l22 * i12);
    const float A22 = 8.0f * (l20 * i02 + l21 * i12 + l22 * i22);

    const float bg = 1.1313708498984762f;  // sqrt(2*8*0.08)

    float* m = g_mats;
    m[ 0 * N_PIX + p] = A00; m[ 1 * N_PIX + p] = A01; m[ 2 * N_PIX + p] = A02;
    m[ 3 * N_PIX + p] = A10; m[ 4 * N_PIX + p] = A11; m[ 5 * N_PIX + p] = A12;
    m[ 6 * N_PIX + p] = A20; m[ 7 * N_PIX + p] = A21; m[ 8 * N_PIX + p] = A22;
    m[ 9 * N_PIX + p] = 8.0f * l00;
    m[10 * N_PIX + p] = 8.0f * l10;
    m[11 * N_PIX + p] = 8.0f * l11;
    m[12 * N_PIX + p] = 8.0f * l20;
    m[13 * N_PIX + p] = 8.0f * l21;
    m[14 * N_PIX + p] = 8.0f * l22;
    m[15 * N_PIX + p] = bg * l00;
    m[16 * N_PIX + p] = bg * (l10 + l11);
    m[17 * N_PIX + p] = bg * (l20 + l21 + l22);
}

// ---------------------------------------------------------------------------
// Kernel 3: streaming apply, float4 pixel-quads, 4 batches per thread.
//   drift_x = A r ; drift_r = -(8L) x - 0.64 r ; diffusion_r = d
// At the measured mixed read/write DRAM ceiling (~6.5 TB/s effective).
// ---------------------------------------------------------------------------
__global__ __launch_bounds__(256) void k_apply(const float4* __restrict__ u4,
                                               float4* __restrict__ out4) {
    const int idx = blockIdx.x * blockDim.x + threadIdx.x;  // 0..262143
    const int q   = idx & (N_Q - 1);
    const int bq  = idx >> 14;  // 0..15

    const float4* m4 = (const float4*)g_mats;
    const float4 A00 = __ldg(m4 +  0 * N_Q + q), A01 = __ldg(m4 +  1 * N_Q + q), A02 = __ldg(m4 +  2 * N_Q + q);
    const float4 A10 = __ldg(m4 +  3 * N_Q + q), A11 = __ldg(m4 +  4 * N_Q + q), A12 = __ldg(m4 +  5 * N_Q + q);
    const float4 A20 = __ldg(m4 +  6 * N_Q + q), A21 = __ldg(m4 +  7 * N_Q + q), A22 = __ldg(m4 +  8 * N_Q + q);
    const float4 L00 = __ldg(m4 +  9 * N_Q + q);
    const float4 L10 = __ldg(m4 + 10 * N_Q + q), L11 = __ldg(m4 + 11 * N_Q + q);
    const float4 L20 = __ldg(m4 + 12 * N_Q + q), L21 = __ldg(m4 + 13 * N_Q + q), L22 = __ldg(m4 + 14 * N_Q + q);
    const float4 D0  = __ldg(m4 + 15 * N_Q + q), D1 = __ldg(m4 + 16 * N_Q + q), D2 = __ldg(m4 + 17 * N_Q + q);

    const size_t diff_off = (size_t)BATCH * 6 * N_Q;  // 6291456 float4
    const float4 zero = make_float4(0.f, 0.f, 0.f, 0.f);
    const float cg = 0.64f;  // 0.64 * G * Ginv == 0.64 * I (fp32 rounding level)

#pragma unroll
    for (int i = 0; i < 4; ++i) {
        const int b = bq * 4 + i;
        const float4* ub = u4 + (size_t)b * (6 * N_Q) + q;
        const float4 x0 = __ldcs(ub);
        const float4 x1 = __ldcs(ub + N_Q);
        const float4 x2 = __ldcs(ub + 2 * N_Q);
        const float4 r0 = __ldcs(ub + 3 * N_Q);
        const float4 r1 = __ldcs(ub + 4 * N_Q);
        const float4 r2 = __ldcs(ub + 5 * N_Q);

        // drift_x = A r
        const float4 dx0 = f4fma(A02, r2, f4fma(A01, r1, f4mul(A00, r0)));
        const float4 dx1 = f4fma(A12, r2, f4fma(A11, r1, f4mul(A10, r0)));
        const float4 dx2 = f4fma(A22, r2, f4fma(A21, r1, f4mul(A20, r0)));
        // drift_r = -( (8L) x + 0.64 r )
        const float4 dr0 = f4neg(f4fma(L00, x0, f4scale(r0, cg)));
        const float4 dr1 = f4neg(f4fma(L11, x1, f4fma(L10, x0, f4scale(r1, cg))));
        const float4 dr2 = f4neg(f4fma(L22, x2, f4fma(L21, x1, f4fma(L20, x0, f4scale(r2, cg)))));

        float4* ob = out4 + (size_t)b * (6 * N_Q) + q;
        __stcs(ob + 0 * N_Q, dx0);
        __stcs(ob + 1 * N_Q, dx1);
        __stcs(ob + 2 * N_Q, dx2);
        __stcs(ob + 3 * N_Q, dr0);
        __stcs(ob + 4 * N_Q, dr1);
        __stcs(ob + 5 * N_Q, dr2);

        float4* db = ob + diff_off;
        __stcs(db + 0 * N_Q, zero);
        __stcs(db + 1 * N_Q, zero);
        __stcs(db + 2 * N_Q, zero);
        __stcs(db + 3 * N_Q, D0);
        __stcs(db + 4 * N_Q, D1);
        __stcs(db + 5 * N_Q, D2);
    }
}

// ---------------------------------------------------------------------------
extern "C" void kernel_launch(void* const* d_in, const int* in_sizes, int n_in,
                              void* d_out, int out_size) {
    const float4* u4 = (const float4*)d_in[0];   // [64, 6, 256, 256]
    const float4* s4 = (const float4*)d_in[1];   // [64, 3, 256, 256]
    const float*  t  = (const float*)d_in[2];    // [64]
    float4* out4 = (float4*)d_out;               // drift + diffusion

    k_covar<<<NBLK_COV, 256>>>(s4);
    k_prep<<<N_PIX / 256, 256>>>(t);
    k_apply<<<(N_Q * 16) / 256, 256>>>(u4, out4);
}

// round 10
// speedup vs baseline: 1.0225x; 1.0225x over previous
#include <cuda_runtime.h>

// Problem constants
#define HW2        65536      // 256*256 pixels
#define N_PIX      65536
#define N_Q        16384      // pixel quads (float4 granularity, apply kernel)
#define BATCH      64
#define NBLK_COV   1024       // 65536 pixels / 64 per block

// Scratch (allocation-free rule: __device__ globals)
__device__ float g_G[6 * N_PIX];       // covariance planes g00,g01,g02,g11,g12,g22
__device__ float g_mats[18 * N_PIX];   // A(9), 8L(6), d(3) — plane-major
__device__ float g_partial[NBLK_COV];  // per-block trace partial sums

// ---- float4 helpers --------------------------------------------------------
__device__ __forceinline__ float4 f4mul(float4 a, float4 b) {
    return make_float4(a.x * b.x, a.y * b.y, a.z * b.z, a.w * b.w);
}
__device__ __forceinline__ float4 f4fma(float4 a, float4 b, float4 c) {
    return make_float4(fmaf(a.x, b.x, c.x), fmaf(a.y, b.y, c.y),
                       fmaf(a.z, b.z, c.z), fmaf(a.w, b.w, c.w));
}
__device__ __forceinline__ float4 f4neg(float4 a) {
    return make_float4(-a.x, -a.y, -a.z, -a.w);
}
__device__ __forceinline__ float4 f4scale(float4 a, float s) {
    return make_float4(a.x * s, a.y * s, a.z * s, a.w * s);
}

// ---------------------------------------------------------------------------
// Kernel 1: per-pixel covariance, scalar accumulators, register-lean.
// Block = 256 threads = 64 pixels x 4 batch-splits (16 batches each).
// In-block smem reduction collapses the 4 split partials — no extra DRAM.
// __launch_bounds__(256,6) caps regs at 42 -> 6 blocks/SM = 48 warps/SM.
// ---------------------------------------------------------------------------
__global__ __launch_bounds__(256, 6) void k_covar(const float* __restrict__ s) {
    const int tid   = threadIdx.x;
    const int px    = tid & 63;          // pixel within block
    const int split = tid >> 6;          // 0..3 (16 batches each)
    const int pix   = blockIdx.x * 64 + px;

    float a0 = 0.f, a1 = 0.f, a2 = 0.f, a3 = 0.f, a4 = 0.f, a5 = 0.f;

    const float* sp = s + pix;
#pragma unroll 4
    for (int i = 0; i < 16; ++i) {
        const int b = split * 16 + i;
        const float* base = sp + (size_t)b * (3 * HW2);
        const float s0 = __ldcs(base);
        const float s1 = __ldcs(base + HW2);
        const float s2 = __ldcs(base + 2 * HW2);
        a0 = fmaf(s0, s0, a0); a1 = fmaf(s0, s1, a1); a2 = fmaf(s0, s2, a2);
        a3 = fmaf(s1, s1, a3); a4 = fmaf(s1, s2, a4); a5 = fmaf(s2, s2, a5);
    }

    __shared__ float sh[4][6][64];       // 6 KB
    sh[split][0][px] = a0; sh[split][1][px] = a1; sh[split][2][px] = a2;
    sh[split][3][px] = a3; sh[split][4][px] = a4; sh[split][5][px] = a5;
    __syncthreads();

    // 384 outputs (6 planes x 64 pixels); each thread handles <=2
    float tr = 0.f;
#pragma unroll
    for (int o = tid; o < 384; o += 256) {
        const int pl = o >> 6;
        const int pq = o & 63;
        const float v = (sh[0][pl][pq] + sh[1][pl][pq] +
                         sh[2][pl][pq] + sh[3][pl][pq]) * (1.0f / 64.0f);
        g_G[(size_t)pl * N_PIX + blockIdx.x * 64 + pq] = v;
        if (pl == 0 || pl == 3 || pl == 5) tr += v;
    }

    // block reduce trace contributions -> one partial per block
#pragma unroll
    for (int o = 16; o > 0; o >>= 1)
        tr += __shfl_down_sync(0xffffffffu, tr, o);
    __shared__ float shr[8];
    const int lane = tid & 31;
    const int w    = tid >> 5;
    if (lane == 0) shr[w] = tr;
    __syncthreads();
    if (tid == 0) {
        float acc = 0.f;
#pragma unroll
        for (int i = 0; i < 8; ++i) acc += shr[i];
        g_partial[blockIdx.x] = acc;
    }
}

// ---------------------------------------------------------------------------
// Kernel 2: per-pixel matrix prep (fp32).
//   G = alpha*G/norm + (1-alpha)*0.25*I
//   A = 8*L*Ginv ; 8L ; d = sqrt(1.28)*rowsum(L)
//   (C = 0.64*G*Ginv == 0.64*I at fp32 rounding — folded into k_apply.)
// ---------------------------------------------------------------------------
__global__ __launch_bounds__(256) void k_prep(const float* __restrict__ t) {
    // reduce 1024 trace partials redundantly per block
    __shared__ float sh_sum;
    {
        float v = g_partial[threadIdx.x]       + g_partial[threadIdx.x + 256]
                + g_partial[threadIdx.x + 512] + g_partial[threadIdx.x + 768];
#pragma unroll
        for (int o = 16; o > 0; o >>= 1)
            v += __shfl_down_sync(0xffffffffu, v, o);
        __shared__ float sh[8];
        const int lane = threadIdx.x & 31;
        const int w    = threadIdx.x >> 5;
        if (lane == 0) sh[w] = v;
        __syncthreads();
        if (threadIdx.x == 0) {
            float acc = 0.f;
#pragma unroll
            for (int i = 0; i < 8; ++i) acc += sh[i];
            sh_sum = acc;
        }
        __syncthreads();
    }

    const int p = blockIdx.x * blockDim.x + threadIdx.x;
    const float t0 = __ldg(t);
    const float diag_mean = sh_sum / (65536.0f * 3.0f);
    const float norm  = (t0 == 1.0f) ? diag_mean * 4.0f : 1.0f;
    const float alpha = 0.5f * __expf(-4.5f * (1.0f - t0));
    const float sa = alpha / norm;
    const float diag_add = (1.0f - alpha) * 0.25f;

    const float a00 = g_G[0 * N_PIX + p] * sa + diag_add;
    const float a01 = g_G[1 * N_PIX + p] * sa;
    const float a02 = g_G[2 * N_PIX + p] * sa;
    const float a11 = g_G[3 * N_PIX + p] * sa + diag_add;
    const float a12 = g_G[4 * N_PIX + p] * sa;
    const float a22 = g_G[5 * N_PIX + p] * sa + diag_add;

    // adjugate inverse (fp32)
    const float c00 = a11 * a22 - a12 * a12;
    const float c01 = a02 * a12 - a01 * a22;
    const float c02 = a01 * a12 - a02 * a11;
    const float det = a00 * c00 + a01 * c01 + a02 * c02;
    const float id  = 1.0f / det;
    const float i00 = c00 * id;
    const float i01 = c01 * id;
    const float i02 = c02 * id;
    const float i11 = (a00 * a22 - a02 * a02) * id;
    const float i12 = (a01 * a02 - a00 * a12) * id;
    const float i22 = (a00 * a11 - a01 * a01) * id;

    // Cholesky (fp32)
    const float l00 = sqrtf(a00);
    const float il00 = 1.0f / l00;
    const float l10 = a01 * il00;
    const float l20 = a02 * il00;
    const float l11 = sqrtf(a11 - l10 * l10);
    const float l21 = (a12 - l20 * l10) / l11;
    const float l22 = sqrtf(a22 - l20 * l20 - l21 * l21);

    // A = 8 * L * Ginv
    const float A00 = 8.0f * (l00 * i00);
    const float A01 = 8.0f * (l00 * i01);
    const float A02 = 8.0f * (l00 * i02);
    const float A10 = 8.0f * (l10 * i00 + l11 * i01);
    const float A11 = 8.0f * (l10 * i01 + l11 * i11);
    const float A12 = 8.0f * (l10 * i02 + l11 * i12);
    const float A20 = 8.0f * (l20 * i00 + l21 * i01 + l22 * i02);
    const float A21 = 8.0f * (l20 * i01 + l21 * i11 + l22 * i12);
    const float A22 = 8.0f * (l20 * i02 + l21 * i12 + l22 * i22);

    const float bg = 1.1313708498984762f;  // sqrt(2*8*0.08)

    float* m = g_mats;
    m[ 0 * N_PIX + p] = A00; m[ 1 * N_PIX + p] = A01; m[ 2 * N_PIX + p] = A02;
    m[ 3 * N_PIX + p] = A10; m[ 4 * N_PIX + p] = A11; m[ 5 * N_PIX + p] = A12;
    m[ 6 * N_PIX + p] = A20; m[ 7 * N_PIX + p] = A21; m[ 8 * N_PIX + p] = A22;
    m[ 9 * N_PIX + p] = 8.0f * l00;
    m[10 * N_PIX + p] = 8.0f * l10;
    m[11 * N_PIX + p] = 8.0f * l11;
    m[12 * N_PIX + p] = 8.0f * l20;
    m[13 * N_PIX + p] = 8.0f * l21;
    m[14 * N_PIX + p] = 8.0f * l22;
    m[15 * N_PIX + p] = bg * l00;
    m[16 * N_PIX + p] = bg * (l10 + l11);
    m[17 * N_PIX + p] = bg * (l20 + l21 + l22);
}

// ---------------------------------------------------------------------------
// Kernel 3: streaming apply, float4 pixel-quads, 4 batches per thread.
//   drift_x = A r ; drift_r = -(8L) x - 0.64 r ; diffusion_r = d
// At the measured mixed read/write DRAM ceiling (~6.5 TB/s effective).
// ---------------------------------------------------------------------------
__global__ __launch_bounds__(256) void k_apply(const float4* __restrict__ u4,
                                               float4* __restrict__ out4) {
    const int idx = blockIdx.x * blockDim.x + threadIdx.x;  // 0..262143
    const int q   = idx & (N_Q - 1);
    const int bq  = idx >> 14;  // 0..15

    const float4* m4 = (const float4*)g_mats;
    const float4 A00 = __ldg(m4 +  0 * N_Q + q), A01 = __ldg(m4 +  1 * N_Q + q), A02 = __ldg(m4 +  2 * N_Q + q);
    const float4 A10 = __ldg(m4 +  3 * N_Q + q), A11 = __ldg(m4 +  4 * N_Q + q), A12 = __ldg(m4 +  5 * N_Q + q);
    const float4 A20 = __ldg(m4 +  6 * N_Q + q), A21 = __ldg(m4 +  7 * N_Q + q), A22 = __ldg(m4 +  8 * N_Q + q);
    const float4 L00 = __ldg(m4 +  9 * N_Q + q);
    const float4 L10 = __ldg(m4 + 10 * N_Q + q), L11 = __ldg(m4 + 11 * N_Q + q);
    const float4 L20 = __ldg(m4 + 12 * N_Q + q), L21 = __ldg(m4 + 13 * N_Q + q), L22 = __ldg(m4 + 14 * N_Q + q);
    const float4 D0  = __ldg(m4 + 15 * N_Q + q), D1 = __ldg(m4 + 16 * N_Q + q), D2 = __ldg(m4 + 17 * N_Q + q);

    const size_t diff_off = (size_t)BATCH * 6 * N_Q;  // 6291456 float4
    const float4 zero = make_float4(0.f, 0.f, 0.f, 0.f);
    const float cg = 0.64f;  // 0.64 * G * Ginv == 0.64 * I (fp32 rounding level)

#pragma unroll
    for (int i = 0; i < 4; ++i) {
        const int b = bq * 4 + i;
        const float4* ub = u4 + (size_t)b * (6 * N_Q) + q;
        const float4 x0 = __ldcs(ub);
        const float4 x1 = __ldcs(ub + N_Q);
        const float4 x2 = __ldcs(ub + 2 * N_Q);
        const float4 r0 = __ldcs(ub + 3 * N_Q);
        const float4 r1 = __ldcs(ub + 4 * N_Q);
        const float4 r2 = __ldcs(ub + 5 * N_Q);

        // drift_x = A r
        const float4 dx0 = f4fma(A02, r2, f4fma(A01, r1, f4mul(A00, r0)));
        const float4 dx1 = f4fma(A12, r2, f4fma(A11, r1, f4mul(A10, r0)));
        const float4 dx2 = f4fma(A22, r2, f4fma(A21, r1, f4mul(A20, r0)));
        // drift_r = -( (8L) x + 0.64 r )
        const float4 dr0 = f4neg(f4fma(L00, x0, f4scale(r0, cg)));
        const float4 dr1 = f4neg(f4fma(L11, x1, f4fma(L10, x0, f4scale(r1, cg))));
        const float4 dr2 = f4neg(f4fma(L22, x2, f4fma(L21, x1, f4fma(L20, x0, f4scale(r2, cg)))));

        float4* ob = out4 + (size_t)b * (6 * N_Q) + q;
        __stcs(ob + 0 * N_Q, dx0);
        __stcs(ob + 1 * N_Q, dx1);
        __stcs(ob + 2 * N_Q, dx2);
        __stcs(ob + 3 * N_Q, dr0);
        __stcs(ob + 4 * N_Q, dr1);
        __stcs(ob + 5 * N_Q, dr2);

        float4* db = ob + diff_off;
        __stcs(db + 0 * N_Q, zero);
        __stcs(db + 1 * N_Q, zero);
        __stcs(db + 2 * N_Q, zero);
        __stcs(db + 3 * N_Q, D0);
        __stcs(db + 4 * N_Q, D1);
        __stcs(db + 5 * N_Q, D2);
    }
}

// ---------------------------------------------------------------------------
extern "C" void kernel_launch(void* const* d_in, const int* in_sizes, int n_in,
                              void* d_out, int out_size) {
    const float4* u4 = (const float4*)d_in[0];   // [64, 6, 256, 256]
    const float*  sx = (const float*)d_in[1];    // [64, 3, 256, 256]
    const float*  t  = (const float*)d_in[2];    // [64]
    float4* out4 = (float4*)d_out;               // drift + diffusion

    k_covar<<<NBLK_COV, 256>>>(sx);
    k_prep<<<N_PIX / 256, 256>>>(t);
    k_apply<<<(N_Q * 16) / 256, 256>>>(u4, out4);
}